// round 12
// baseline (speedup 1.0000x reference)
#include <cuda_runtime.h>
#include <cstdint>

#define N_NODES 50000
#define N_EDGES 1600000
#define IN_DIM 64
#define HD 64
#define NUM_HEADS 4
#define OUT_DIM 16

// ---------------- device scratch ----------------
__device__ float g_Q[N_NODES * HD];
__device__ float g_K[N_NODES * HD];
__device__ float g_V[N_NODES * HD];
__device__ float g_Z[N_NODES * NUM_HEADS];

// ---------------- helpers ----------------
__device__ __forceinline__ void red_add_v4(float* p, float a, float b, float c, float d) {
    asm volatile("red.global.add.v4.f32 [%0], {%1,%2,%3,%4};"
                 :: "l"(p), "f"(a), "f"(b), "f"(c), "f"(d) : "memory");
}
__device__ __forceinline__ uint32_t f2tf32(float f) {
    uint32_t r;
    asm("cvt.rna.tf32.f32 %0, %1;" : "=r"(r) : "f"(f));
    return r;
}
__device__ __forceinline__ void mma_tf32(float d[4], uint32_t a0, uint32_t a1,
                                         uint32_t a2, uint32_t a3,
                                         uint32_t b0, uint32_t b1) {
    asm("mma.sync.aligned.m16n8k8.row.col.f32.tf32.tf32.f32 "
        "{%0,%1,%2,%3}, {%4,%5,%6,%7}, {%8,%9}, {%0,%1,%2,%3};"
        : "+f"(d[0]), "+f"(d[1]), "+f"(d[2]), "+f"(d[3])
        : "r"(a0), "r"(a1), "r"(a2), "r"(a3), "r"(b0), "r"(b1));
}

// ---------------- zero init ----------------
__global__ void zero_kernel(float* __restrict__ out) {
    int i = blockIdx.x * blockDim.x + threadIdx.x;
    if (i < N_NODES * HD) out[i] = 0.0f;
    if (i < N_NODES * NUM_HEADS) g_Z[i] = 0.0f;
}

// ---------------- node projections (R3 scalar, known good) ----------------
#define PROJ_SMEM_FLOATS (128 * 65 + 64 * 64 + 64)
__global__ __launch_bounds__(128)
void proj_kernel(const float* __restrict__ x,
                 const float* __restrict__ WQ, const float* __restrict__ bQ,
                 const float* __restrict__ WK, const float* __restrict__ bK,
                 const float* __restrict__ WV, const float* __restrict__ bV) {
    const float* W; const float* b; float* out;
    if (blockIdx.y == 0)      { W = WQ; b = bQ; out = g_Q; }
    else if (blockIdx.y == 1) { W = WK; b = bK; out = g_K; }
    else                      { W = WV; b = bV; out = g_V; }

    extern __shared__ float sm[];
    float* x_s = sm;
    float* w_s = sm + 128 * 65;
    float* b_s = w_s + 64 * 64;

    const int tid = threadIdx.x;
    const int base = blockIdx.x * 128;

    {
        const float4* W4 = reinterpret_cast<const float4*>(W);
        float4* ws4 = reinterpret_cast<float4*>(w_s);
        #pragma unroll
        for (int i = tid; i < 1024; i += 128) ws4[i] = W4[i];
    }
    if (tid < 64) b_s[tid] = b[tid];

    for (int f = tid; f < 128 * 16; f += 128) {
        int r = f >> 4, q = f & 15;
        int gr = base + r;
        if (gr >= N_NODES) gr = N_NODES - 1;
        float4 v = reinterpret_cast<const float4*>(x + (size_t)gr * 64)[q];
        float* d = x_s + r * 65 + q * 4;
        d[0] = v.x; d[1] = v.y; d[2] = v.z; d[3] = v.w;
    }
    __syncthreads();

    const int eg = tid >> 3, dg = tid & 7;

    float acc[8][8];
    #pragma unroll
    for (int i = 0; i < 8; i++)
        #pragma unroll
        for (int j = 0; j < 8; j++) acc[i][j] = 0.0f;

    const float4* ws4 = reinterpret_cast<const float4*>(w_s);
    #pragma unroll 4
    for (int c = 0; c < 64; c++) {
        float4 w0 = ws4[c * 16 + dg * 2];
        float4 w1 = ws4[c * 16 + dg * 2 + 1];
        float a[8];
        #pragma unroll
        for (int i = 0; i < 8; i++) a[i] = x_s[(eg * 8 + i) * 65 + c];
        #pragma unroll
        for (int i = 0; i < 8; i++) {
            acc[i][0] += a[i] * w0.x; acc[i][1] += a[i] * w0.y;
            acc[i][2] += a[i] * w0.z; acc[i][3] += a[i] * w0.w;
            acc[i][4] += a[i] * w1.x; acc[i][5] += a[i] * w1.y;
            acc[i][6] += a[i] * w1.z; acc[i][7] += a[i] * w1.w;
        }
    }

    float bb[8];
    #pragma unroll
    for (int j = 0; j < 8; j++) bb[j] = b_s[dg * 8 + j];
    #pragma unroll
    for (int i = 0; i < 8; i++) {
        int n = base + eg * 8 + i;
        if (n < N_NODES) {
            float4 o0 = make_float4(acc[i][0] + bb[0], acc[i][1] + bb[1], acc[i][2] + bb[2], acc[i][3] + bb[3]);
            float4 o1 = make_float4(acc[i][4] + bb[4], acc[i][5] + bb[5], acc[i][6] + bb[6], acc[i][7] + bb[7]);
            float4* dst = reinterpret_cast<float4*>(out + (size_t)n * 64 + dg * 8);
            dst[0] = o0; dst[1] = o1;
        }
    }
}

// ---------------- fused edge kernel: 128-edge tiles, 256 threads, 32 warps/SM ----
#define TILE_E   128
#define EA_OFF   0               // 128 rows x stride 68 (tf32 in, fp32 E out)
#define EA_STR   68
#define W_OFF    (TILE_E * 68)   // 64 rows(k) x stride 72
#define W_STR    72
#define BIAS_OFF (W_OFF + 64 * 72)
#define SI_OFF   (BIAS_OFF + 64)          // 128 ints
#define DI_OFF   (SI_OFF + TILE_E)        // 128 ints
#define EDGE_SMEM_FLOATS (DI_OFF + TILE_E)

__global__ __launch_bounds__(256, 4)
void edge_kernel(const float* __restrict__ ea,
                 const int* __restrict__ eidx,
                 const float* __restrict__ WE, const float* __restrict__ bE,
                 float* __restrict__ out) {
    extern __shared__ float sm[];
    uint32_t* ea_s = reinterpret_cast<uint32_t*>(sm + EA_OFF);
    float* E_s     = sm + EA_OFF;               // reused after MMA
    uint32_t* w_s  = reinterpret_cast<uint32_t*>(sm + W_OFF);
    float* bias_s  = sm + BIAS_OFF;
    int* si_s      = reinterpret_cast<int*>(sm + SI_OFF);
    int* di_s      = reinterpret_cast<int*>(sm + DI_OFF);

    const int tid = threadIdx.x;
    const int base = blockIdx.x * TILE_E;

    if (tid < 64) bias_s[tid] = bE[tid];
    if (tid < TILE_E) {
        si_s[tid] = eidx[base + tid];
        di_s[tid] = eidx[N_EDGES + base + tid];
    }

    // stage A = ea tile (tf32 bits), stride 68 : 2048 float4 / 256 thr = 8 iters
    for (int f = tid; f < TILE_E * 16; f += 256) {
        int r = f >> 4, q = f & 15;
        float4 v = reinterpret_cast<const float4*>(ea + (size_t)(base + r) * 64)[q];
        uint4 t;
        t.x = f2tf32(v.x); t.y = f2tf32(v.y); t.z = f2tf32(v.z); t.w = f2tf32(v.w);
        *reinterpret_cast<uint4*>(ea_s + r * EA_STR + q * 4) = t;
    }
    // stage B = WE (row-major [k][n]) as tf32 bits, stride 72
    for (int f = tid; f < 64 * 16; f += 256) {
        int k = f >> 4, q = f & 15;
        float4 v = reinterpret_cast<const float4*>(WE + (size_t)k * 64)[q];
        uint4 t;
        t.x = f2tf32(v.x); t.y = f2tf32(v.y); t.z = f2tf32(v.z); t.w = f2tf32(v.w);
        *reinterpret_cast<uint4*>(w_s + k * W_STR + q * 4) = t;
    }
    __syncthreads();

    const int lane = tid & 31;
    const int warp = tid >> 5;    // 0..7
    const int g  = lane >> 2;
    const int tg = lane & 3;
    const int wrow = warp * 16;   // one m16 tile per warp

    // ---- Phase A: E = ea @ WE via m16n8k8 tf32 mma ----
    float acc[8][4];
    #pragma unroll
    for (int nt = 0; nt < 8; nt++)
        #pragma unroll
        for (int j = 0; j < 4; j++) acc[nt][j] = 0.0f;

    #pragma unroll
    for (int k8 = 0; k8 < 8; k8++) {
        const int r0 = wrow + g;
        uint32_t a0 = ea_s[(r0)     * EA_STR + k8 * 8 + tg];
        uint32_t a1 = ea_s[(r0 + 8) * EA_STR + k8 * 8 + tg];
        uint32_t a2 = ea_s[(r0)     * EA_STR + k8 * 8 + tg + 4];
        uint32_t a3 = ea_s[(r0 + 8) * EA_STR + k8 * 8 + tg + 4];
        #pragma unroll
        for (int nt = 0; nt < 8; nt++) {
            uint32_t b0 = w_s[(k8 * 8 + tg)     * W_STR + nt * 8 + g];
            uint32_t b1 = w_s[(k8 * 8 + tg + 4) * W_STR + nt * 8 + g];
            mma_tf32(acc[nt], a0, a1, a2, a3, b0, b1);
        }
    }

    // ---- store E (+bias) into this warp's own rows (no sync needed) ----
    #pragma unroll
    for (int rr = 0; rr < 2; rr++) {
        const int row = wrow + rr * 8 + g;
        #pragma unroll
        for (int nt = 0; nt < 8; nt++) {
            const int c0 = nt * 8 + tg * 2;
            float2 bb = *reinterpret_cast<const float2*>(bias_s + c0);
            *reinterpret_cast<float2*>(E_s + row * EA_STR + c0) =
                make_float2(acc[nt][rr * 2 + 0] + bb.x,
                            acc[nt][rr * 2 + 1] + bb.y);
        }
    }
    __syncthreads();

    // ---- Phase B: per (edge, head): score + scatter, all float4. 2 passes ----
    #pragma unroll
    for (int pass = 0; pass < 2; pass++) {
        const int le = pass * 64 + (tid >> 2);
        const int h  = tid & 3;
        const int src = si_s[le];
        const int dst = di_s[le];

        const float4* Kp = reinterpret_cast<const float4*>(g_K + (size_t)src * 64 + h * 16);
        const float4* Qp = reinterpret_cast<const float4*>(g_Q + (size_t)dst * 64 + h * 16);
        const float4* Ep = reinterpret_cast<const float4*>(E_s + le * EA_STR + h * 16);

        float p = 0.0f;
        #pragma unroll
        for (int q = 0; q < 4; q++) {
            float4 k = Kp[q];
            float4 qv = Qp[q];
            float4 e = Ep[q];
            p += k.x * qv.x * e.x + k.y * qv.y * e.y + k.z * qv.z * e.z + k.w * qv.w * e.w;
        }
        float s = __expf(fminf(fmaxf(p * 0.25f, -5.0f), 5.0f));

        const float4* Vp = reinterpret_cast<const float4*>(g_V + (size_t)src * 64 + h * 16);
        float* ob = out + (size_t)dst * 64 + h * 16;
        #pragma unroll
        for (int q = 0; q < 4; q++) {
            float4 v = Vp[q];
            red_add_v4(ob + q * 4, v.x * s, v.y * s, v.z * s, v.w * s);
        }
        // Z: one red.v4 per edge (quad gather to h==0 lane)
        const int qbase = (tid & 31) & ~3;
        float s0 = __shfl_sync(0xffffffffu, s, qbase);
        float s1 = __shfl_sync(0xffffffffu, s, qbase + 1);
        float s2 = __shfl_sync(0xffffffffu, s, qbase + 2);
        float s3 = __shfl_sync(0xffffffffu, s, qbase + 3);
        if (h == 0)
            red_add_v4(g_Z + (size_t)dst * 4, s0, s1, s2, s3);
    }
}

// ---------------- finalize ----------------
__global__ void finalize_kernel(float* __restrict__ out) {
    int i = blockIdx.x * blockDim.x + threadIdx.x;
    if (i < N_NODES * HD) {
        int n = i >> 6;
        int h = (i >> 4) & 3;
        out[i] = out[i] / (g_Z[n * 4 + h] + 1e-6f);
    }
}

// ---------------- launch ----------------
extern "C" void kernel_launch(void* const* d_in, const int* in_sizes, int n_in,
                              void* d_out, int out_size) {
    const float* x   = (const float*)d_in[0];
    const float* ea  = (const float*)d_in[1];
    const int*   ei  = (const int*)  d_in[2];
    const float* WQ  = (const float*)d_in[3];
    const float* bQ  = (const float*)d_in[4];
    const float* WK  = (const float*)d_in[5];
    const float* bK  = (const float*)d_in[6];
    const float* WE  = (const float*)d_in[7];
    const float* bE  = (const float*)d_in[8];
    const float* WV  = (const float*)d_in[9];
    const float* bV  = (const float*)d_in[10];
    float* out = (float*)d_out;

    static_assert(EDGE_SMEM_FLOATS * 4 * 4 < 228 * 1024, "smem occupancy");
    cudaFuncSetAttribute(edge_kernel, cudaFuncAttributeMaxDynamicSharedMemorySize,
                         EDGE_SMEM_FLOATS * (int)sizeof(float));
    cudaFuncSetAttribute(proj_kernel, cudaFuncAttributeMaxDynamicSharedMemorySize,
                         PROJ_SMEM_FLOATS * (int)sizeof(float));

    zero_kernel<<<(N_NODES * HD + 255) / 256, 256>>>(out);
    {
        dim3 grid((N_NODES + 127) / 128, 3);
        proj_kernel<<<grid, 128, PROJ_SMEM_FLOATS * sizeof(float)>>>(x, WQ, bQ, WK, bK, WV, bV);
    }
    edge_kernel<<<N_EDGES / TILE_E, 256, EDGE_SMEM_FLOATS * sizeof(float)>>>(ea, ei, WE, bE, out);
    finalize_kernel<<<(N_NODES * HD + 255) / 256, 256>>>(out);
}

// round 13
// speedup vs baseline: 1.0418x; 1.0418x over previous
#include <cuda_runtime.h>
#include <cstdint>

#define N_NODES 50000
#define N_EDGES 1600000
#define IN_DIM 64
#define HD 64
#define NUM_HEADS 4
#define OUT_DIM 16

// ---------------- device scratch ----------------
__device__ float g_Q[N_NODES * HD];
__device__ float g_K[N_NODES * HD];
__device__ float g_V[N_NODES * HD];
__device__ float g_Z[N_NODES * NUM_HEADS];

// ---------------- helpers ----------------
__device__ __forceinline__ void red_add_v4(float* p, float a, float b, float c, float d) {
    asm volatile("red.global.add.v4.f32 [%0], {%1,%2,%3,%4};"
                 :: "l"(p), "f"(a), "f"(b), "f"(c), "f"(d) : "memory");
}
__device__ __forceinline__ uint32_t f2tf32(float f) {
    uint32_t r;
    asm("cvt.rna.tf32.f32 %0, %1;" : "=r"(r) : "f"(f));
    return r;
}
__device__ __forceinline__ void mma_tf32(float d[4], uint32_t a0, uint32_t a1,
                                         uint32_t a2, uint32_t a3,
                                         uint32_t b0, uint32_t b1) {
    asm("mma.sync.aligned.m16n8k8.row.col.f32.tf32.tf32.f32 "
        "{%0,%1,%2,%3}, {%4,%5,%6,%7}, {%8,%9}, {%0,%1,%2,%3};"
        : "+f"(d[0]), "+f"(d[1]), "+f"(d[2]), "+f"(d[3])
        : "r"(a0), "r"(a1), "r"(a2), "r"(a3), "r"(b0), "r"(b1));
}

// ---------------- zero init ----------------
__global__ void zero_kernel(float* __restrict__ out) {
    int i = blockIdx.x * blockDim.x + threadIdx.x;
    if (i < N_NODES * HD) out[i] = 0.0f;
    if (i < N_NODES * NUM_HEADS) g_Z[i] = 0.0f;
}

// ---------------- node projections (R3 scalar, known good) ----------------
#define PROJ_SMEM_FLOATS (128 * 65 + 64 * 64 + 64)
__global__ __launch_bounds__(128)
void proj_kernel(const float* __restrict__ x,
                 const float* __restrict__ WQ, const float* __restrict__ bQ,
                 const float* __restrict__ WK, const float* __restrict__ bK,
                 const float* __restrict__ WV, const float* __restrict__ bV) {
    const float* W; const float* b; float* out;
    if (blockIdx.y == 0)      { W = WQ; b = bQ; out = g_Q; }
    else if (blockIdx.y == 1) { W = WK; b = bK; out = g_K; }
    else                      { W = WV; b = bV; out = g_V; }

    extern __shared__ float sm[];
    float* x_s = sm;
    float* w_s = sm + 128 * 65;
    float* b_s = w_s + 64 * 64;

    const int tid = threadIdx.x;
    const int base = blockIdx.x * 128;

    {
        const float4* W4 = reinterpret_cast<const float4*>(W);
        float4* ws4 = reinterpret_cast<float4*>(w_s);
        #pragma unroll
        for (int i = tid; i < 1024; i += 128) ws4[i] = W4[i];
    }
    if (tid < 64) b_s[tid] = b[tid];

    for (int f = tid; f < 128 * 16; f += 128) {
        int r = f >> 4, q = f & 15;
        int gr = base + r;
        if (gr >= N_NODES) gr = N_NODES - 1;
        float4 v = reinterpret_cast<const float4*>(x + (size_t)gr * 64)[q];
        float* d = x_s + r * 65 + q * 4;
        d[0] = v.x; d[1] = v.y; d[2] = v.z; d[3] = v.w;
    }
    __syncthreads();

    const int eg = tid >> 3, dg = tid & 7;

    float acc[8][8];
    #pragma unroll
    for (int i = 0; i < 8; i++)
        #pragma unroll
        for (int j = 0; j < 8; j++) acc[i][j] = 0.0f;

    const float4* ws4 = reinterpret_cast<const float4*>(w_s);
    #pragma unroll 4
    for (int c = 0; c < 64; c++) {
        float4 w0 = ws4[c * 16 + dg * 2];
        float4 w1 = ws4[c * 16 + dg * 2 + 1];
        float a[8];
        #pragma unroll
        for (int i = 0; i < 8; i++) a[i] = x_s[(eg * 8 + i) * 65 + c];
        #pragma unroll
        for (int i = 0; i < 8; i++) {
            acc[i][0] += a[i] * w0.x; acc[i][1] += a[i] * w0.y;
            acc[i][2] += a[i] * w0.z; acc[i][3] += a[i] * w0.w;
            acc[i][4] += a[i] * w1.x; acc[i][5] += a[i] * w1.y;
            acc[i][6] += a[i] * w1.z; acc[i][7] += a[i] * w1.w;
        }
    }

    float bb[8];
    #pragma unroll
    for (int j = 0; j < 8; j++) bb[j] = b_s[dg * 8 + j];
    #pragma unroll
    for (int i = 0; i < 8; i++) {
        int n = base + eg * 8 + i;
        if (n < N_NODES) {
            float4 o0 = make_float4(acc[i][0] + bb[0], acc[i][1] + bb[1], acc[i][2] + bb[2], acc[i][3] + bb[3]);
            float4 o1 = make_float4(acc[i][4] + bb[4], acc[i][5] + bb[5], acc[i][6] + bb[6], acc[i][7] + bb[7]);
            float4* dst = reinterpret_cast<float4*>(out + (size_t)n * 64 + dg * 8);
            dst[0] = o0; dst[1] = o1;
        }
    }
}

// ---------------- fused edge kernel: 64-edge tiles, 6 blocks/SM = 24 warps ----
#define TILE_E   64
#define EA_OFF   0            // 64 rows x stride 68
#define EA_STR   68
#define W_OFF    (TILE_E * 68)   // 64 rows(k) x stride 72
#define W_STR    72
#define BIAS_OFF (W_OFF + 64 * 72)        // 64
#define SI_OFF   (BIAS_OFF + 64)          // 64 ints
#define DI_OFF   (SI_OFF + TILE_E)        // 64 ints
#define EDGE_SMEM_FLOATS (DI_OFF + TILE_E)

__global__ __launch_bounds__(128, 6)
void edge_kernel(const float* __restrict__ ea,
                 const int* __restrict__ eidx,
                 const float* __restrict__ WE, const float* __restrict__ bE,
                 float* __restrict__ out) {
    extern __shared__ float sm[];
    uint32_t* ea_s = reinterpret_cast<uint32_t*>(sm + EA_OFF);
    float* E_s     = sm + EA_OFF;               // reused after MMA
    uint32_t* w_s  = reinterpret_cast<uint32_t*>(sm + W_OFF);
    float* bias_s  = sm + BIAS_OFF;
    int* si_s      = reinterpret_cast<int*>(sm + SI_OFF);
    int* di_s      = reinterpret_cast<int*>(sm + DI_OFF);

    const int tid = threadIdx.x;
    const int base = blockIdx.x * TILE_E;

    if (tid < 64) bias_s[tid] = bE[tid];
    if (tid < TILE_E) {
        si_s[tid] = eidx[base + tid];
        di_s[tid] = eidx[N_EDGES + base + tid];
    }

    // stage A = ea tile (tf32 bits), stride 68
    for (int f = tid; f < TILE_E * 16; f += 128) {
        int r = f >> 4, q = f & 15;
        float4 v = reinterpret_cast<const float4*>(ea + (size_t)(base + r) * 64)[q];
        uint4 t;
        t.x = f2tf32(v.x); t.y = f2tf32(v.y); t.z = f2tf32(v.z); t.w = f2tf32(v.w);
        *reinterpret_cast<uint4*>(ea_s + r * EA_STR + q * 4) = t;
    }
    // stage B = WE (row-major [k][n]) as tf32 bits, stride 72
    for (int f = tid; f < 64 * 16; f += 128) {
        int k = f >> 4, q = f & 15;
        float4 v = reinterpret_cast<const float4*>(WE + (size_t)k * 64)[q];
        uint4 t;
        t.x = f2tf32(v.x); t.y = f2tf32(v.y); t.z = f2tf32(v.z); t.w = f2tf32(v.w);
        *reinterpret_cast<uint4*>(w_s + k * W_STR + q * 4) = t;
    }
    __syncthreads();

    const int lane = tid & 31;
    const int warp = tid >> 5;
    const int g  = lane >> 2;   // 0..7
    const int tg = lane & 3;    // 0..3
    const int wrow = warp * 16; // this warp's 16 edges

    // ---- Phase A: E = ea @ WE via m16n8k8 tf32 mma (one m-tile per warp) ----
    float acc[8][4];
    #pragma unroll
    for (int nt = 0; nt < 8; nt++)
        #pragma unroll
        for (int j = 0; j < 4; j++) acc[nt][j] = 0.0f;

    #pragma unroll
    for (int k8 = 0; k8 < 8; k8++) {
        const int r0 = wrow + g;
        uint32_t a0 = ea_s[(r0)     * EA_STR + k8 * 8 + tg];
        uint32_t a1 = ea_s[(r0 + 8) * EA_STR + k8 * 8 + tg];
        uint32_t a2 = ea_s[(r0)     * EA_STR + k8 * 8 + tg + 4];
        uint32_t a3 = ea_s[(r0 + 8) * EA_STR + k8 * 8 + tg + 4];
        #pragma unroll
        for (int nt = 0; nt < 8; nt++) {
            uint32_t b0 = w_s[(k8 * 8 + tg)     * W_STR + nt * 8 + g];
            uint32_t b1 = w_s[(k8 * 8 + tg + 4) * W_STR + nt * 8 + g];
            mma_tf32(acc[nt], a0, a1, a2, a3, b0, b1);
        }
    }

    // ---- store E (+bias) into this warp's own rows (no sync needed) ----
    #pragma unroll
    for (int rr = 0; rr < 2; rr++) {
        const int row = wrow + rr * 8 + g;
        #pragma unroll
        for (int nt = 0; nt < 8; nt++) {
            const int c0 = nt * 8 + tg * 2;
            float2 bb = *reinterpret_cast<const float2*>(bias_s + c0);
            *reinterpret_cast<float2*>(E_s + row * EA_STR + c0) =
                make_float2(acc[nt][rr * 2 + 0] + bb.x,
                            acc[nt][rr * 2 + 1] + bb.y);
        }
    }
    __syncthreads();

    // ---- Phase B: per (edge, head): score + scatter, all float4 ----
    #pragma unroll
    for (int pass = 0; pass < 2; pass++) {
        const int le = pass * 32 + (tid >> 2);
        const int h  = tid & 3;
        const int src = si_s[le];
        const int dst = di_s[le];

        const float4* Kp = reinterpret_cast<const float4*>(g_K + (size_t)src * 64 + h * 16);
        const float4* Qp = reinterpret_cast<const float4*>(g_Q + (size_t)dst * 64 + h * 16);
        const float4* Ep = reinterpret_cast<const float4*>(E_s + le * EA_STR + h * 16);

        float p = 0.0f;
        #pragma unroll
        for (int q = 0; q < 4; q++) {
            float4 k = Kp[q];
            float4 qv = Qp[q];
            float4 e = Ep[q];
            p += k.x * qv.x * e.x + k.y * qv.y * e.y + k.z * qv.z * e.z + k.w * qv.w * e.w;
        }
        float s = __expf(fminf(fmaxf(p * 0.25f, -5.0f), 5.0f));

        const float4* Vp = reinterpret_cast<const float4*>(g_V + (size_t)src * 64 + h * 16);
        float* ob = out + (size_t)dst * 64 + h * 16;
        #pragma unroll
        for (int q = 0; q < 4; q++) {
            float4 v = Vp[q];
            red_add_v4(ob + q * 4, v.x * s, v.y * s, v.z * s, v.w * s);
        }
        // Z: one red.v4 per edge (gather the quad's 4 head scores to h==0 lane)
        const int qbase = (tid & 31) & ~3;
        float s0 = __shfl_sync(0xffffffffu, s, qbase);
        float s1 = __shfl_sync(0xffffffffu, s, qbase + 1);
        float s2 = __shfl_sync(0xffffffffu, s, qbase + 2);
        float s3 = __shfl_sync(0xffffffffu, s, qbase + 3);
        if (h == 0)
            red_add_v4(g_Z + (size_t)dst * 4, s0, s1, s2, s3);
    }
}

// ---------------- finalize ----------------
__global__ void finalize_kernel(float* __restrict__ out) {
    int i = blockIdx.x * blockDim.x + threadIdx.x;
    if (i < N_NODES * HD) {
        int n = i >> 6;
        int h = (i >> 4) & 3;
        out[i] = out[i] / (g_Z[n * 4 + h] + 1e-6f);
    }
}

// ---------------- launch ----------------
extern "C" void kernel_launch(void* const* d_in, const int* in_sizes, int n_in,
                              void* d_out, int out_size) {
    const float* x   = (const float*)d_in[0];
    const float* ea  = (const float*)d_in[1];
    const int*   ei  = (const int*)  d_in[2];
    const float* WQ  = (const float*)d_in[3];
    const float* bQ  = (const float*)d_in[4];
    const float* WK  = (const float*)d_in[5];
    const float* bK  = (const float*)d_in[6];
    const float* WE  = (const float*)d_in[7];
    const float* bE  = (const float*)d_in[8];
    const float* WV  = (const float*)d_in[9];
    const float* bV  = (const float*)d_in[10];
    float* out = (float*)d_out;

    static_assert(EDGE_SMEM_FLOATS * 4 * 6 < 228 * 1024, "smem occupancy");
    cudaFuncSetAttribute(edge_kernel, cudaFuncAttributeMaxDynamicSharedMemorySize,
                         EDGE_SMEM_FLOATS * (int)sizeof(float));
    cudaFuncSetAttribute(proj_kernel, cudaFuncAttributeMaxDynamicSharedMemorySize,
                         PROJ_SMEM_FLOATS * (int)sizeof(float));

    zero_kernel<<<(N_NODES * HD + 255) / 256, 256>>>(out);
    {
        dim3 grid((N_NODES + 127) / 128, 3);
        proj_kernel<<<grid, 128, PROJ_SMEM_FLOATS * sizeof(float)>>>(x, WQ, bQ, WK, bK, WV, bV);
    }
    edge_kernel<<<N_EDGES / TILE_E, 128, EDGE_SMEM_FLOATS * sizeof(float)>>>(ea, ei, WE, bE, out);
    finalize_kernel<<<(N_NODES * HD + 255) / 256, 256>>>(out);
}

// round 14
// speedup vs baseline: 1.1186x; 1.0736x over previous
#include <cuda_runtime.h>
#include <cstdint>

#define N_NODES 50000
#define N_EDGES 1600000
#define IN_DIM 64
#define HD 64
#define NUM_HEADS 4
#define OUT_DIM 16

// ---------------- device scratch ----------------
__device__ float g_Q[N_NODES * HD];
__device__ float g_K[N_NODES * HD];
__device__ float g_V[N_NODES * HD];
__device__ float g_Z[N_NODES * NUM_HEADS];

// ---------------- helpers ----------------
__device__ __forceinline__ void red_add_v4(float* p, float a, float b, float c, float d) {
    asm volatile("red.global.add.v4.f32 [%0], {%1,%2,%3,%4};"
                 :: "l"(p), "f"(a), "f"(b), "f"(c), "f"(d) : "memory");
}
__device__ __forceinline__ uint32_t f2tf32(float f) {
    uint32_t r;
    asm("cvt.rna.tf32.f32 %0, %1;" : "=r"(r) : "f"(f));
    return r;
}
__device__ __forceinline__ void mma_tf32(float d[4], uint32_t a0, uint32_t a1,
                                         uint32_t a2, uint32_t a3,
                                         uint32_t b0, uint32_t b1) {
    asm("mma.sync.aligned.m16n8k8.row.col.f32.tf32.tf32.f32 "
        "{%0,%1,%2,%3}, {%4,%5,%6,%7}, {%8,%9}, {%0,%1,%2,%3};"
        : "+f"(d[0]), "+f"(d[1]), "+f"(d[2]), "+f"(d[3])
        : "r"(a0), "r"(a1), "r"(a2), "r"(a3), "r"(b0), "r"(b1));
}

// ---------------- zero init ----------------
__global__ void zero_kernel(float* __restrict__ out) {
    int i = blockIdx.x * blockDim.x + threadIdx.x;
    if (i < N_NODES * HD) out[i] = 0.0f;
    if (i < N_NODES * NUM_HEADS) g_Z[i] = 0.0f;
}

// ---------------- node projections (R3 scalar, known good) ----------------
#define PROJ_SMEM_FLOATS (128 * 65 + 64 * 64 + 64)
__global__ __launch_bounds__(128)
void proj_kernel(const float* __restrict__ x,
                 const float* __restrict__ WQ, const float* __restrict__ bQ,
                 const float* __restrict__ WK, const float* __restrict__ bK,
                 const float* __restrict__ WV, const float* __restrict__ bV) {
    const float* W; const float* b; float* out;
    if (blockIdx.y == 0)      { W = WQ; b = bQ; out = g_Q; }
    else if (blockIdx.y == 1) { W = WK; b = bK; out = g_K; }
    else                      { W = WV; b = bV; out = g_V; }

    extern __shared__ float sm[];
    float* x_s = sm;
    float* w_s = sm + 128 * 65;
    float* b_s = w_s + 64 * 64;

    const int tid = threadIdx.x;
    const int base = blockIdx.x * 128;

    {
        const float4* W4 = reinterpret_cast<const float4*>(W);
        float4* ws4 = reinterpret_cast<float4*>(w_s);
        #pragma unroll
        for (int i = tid; i < 1024; i += 128) ws4[i] = W4[i];
    }
    if (tid < 64) b_s[tid] = b[tid];

    for (int f = tid; f < 128 * 16; f += 128) {
        int r = f >> 4, q = f & 15;
        int gr = base + r;
        if (gr >= N_NODES) gr = N_NODES - 1;
        float4 v = reinterpret_cast<const float4*>(x + (size_t)gr * 64)[q];
        float* d = x_s + r * 65 + q * 4;
        d[0] = v.x; d[1] = v.y; d[2] = v.z; d[3] = v.w;
    }
    __syncthreads();

    const int eg = tid >> 3, dg = tid & 7;

    float acc[8][8];
    #pragma unroll
    for (int i = 0; i < 8; i++)
        #pragma unroll
        for (int j = 0; j < 8; j++) acc[i][j] = 0.0f;

    const float4* ws4 = reinterpret_cast<const float4*>(w_s);
    #pragma unroll 4
    for (int c = 0; c < 64; c++) {
        float4 w0 = ws4[c * 16 + dg * 2];
        float4 w1 = ws4[c * 16 + dg * 2 + 1];
        float a[8];
        #pragma unroll
        for (int i = 0; i < 8; i++) a[i] = x_s[(eg * 8 + i) * 65 + c];
        #pragma unroll
        for (int i = 0; i < 8; i++) {
            acc[i][0] += a[i] * w0.x; acc[i][1] += a[i] * w0.y;
            acc[i][2] += a[i] * w0.z; acc[i][3] += a[i] * w0.w;
            acc[i][4] += a[i] * w1.x; acc[i][5] += a[i] * w1.y;
            acc[i][6] += a[i] * w1.z; acc[i][7] += a[i] * w1.w;
        }
    }

    float bb[8];
    #pragma unroll
    for (int j = 0; j < 8; j++) bb[j] = b_s[dg * 8 + j];
    #pragma unroll
    for (int i = 0; i < 8; i++) {
        int n = base + eg * 8 + i;
        if (n < N_NODES) {
            float4 o0 = make_float4(acc[i][0] + bb[0], acc[i][1] + bb[1], acc[i][2] + bb[2], acc[i][3] + bb[3]);
            float4 o1 = make_float4(acc[i][4] + bb[4], acc[i][5] + bb[5], acc[i][6] + bb[6], acc[i][7] + bb[7]);
            float4* dst = reinterpret_cast<float4*>(out + (size_t)n * 64 + dg * 8);
            dst[0] = o0; dst[1] = o1;
        }
    }
}

// ---------------- fused edge kernel: R9 structure + streaming (__ldcs) ea/eidx ----
#define TILE_E   64
#define EA_OFF   0            // 64 rows x stride 68
#define EA_STR   68
#define W_OFF    (TILE_E * 68)   // 64 rows(k) x stride 72
#define W_STR    72
#define BIAS_OFF (W_OFF + 64 * 72)        // 64
#define SI_OFF   (BIAS_OFF + 64)          // 64 ints
#define DI_OFF   (SI_OFF + TILE_E)        // 64 ints
#define EDGE_SMEM_FLOATS (DI_OFF + TILE_E)

__global__ __launch_bounds__(128, 5)
void edge_kernel(const float* __restrict__ ea,
                 const int* __restrict__ eidx,
                 const float* __restrict__ WE, const float* __restrict__ bE,
                 float* __restrict__ out) {
    extern __shared__ float sm[];
    uint32_t* ea_s = reinterpret_cast<uint32_t*>(sm + EA_OFF);
    float* E_s     = sm + EA_OFF;               // reused after MMA
    uint32_t* w_s  = reinterpret_cast<uint32_t*>(sm + W_OFF);
    float* bias_s  = sm + BIAS_OFF;
    int* si_s      = reinterpret_cast<int*>(sm + SI_OFF);
    int* di_s      = reinterpret_cast<int*>(sm + DI_OFF);

    const int tid = threadIdx.x;
    const int base = blockIdx.x * TILE_E;

    if (tid < 64) bias_s[tid] = bE[tid];
    if (tid < TILE_E) {
        si_s[tid] = __ldcs(eidx + base + tid);              // streaming: don't pollute L2
        di_s[tid] = __ldcs(eidx + N_EDGES + base + tid);
    }

    // stage A = ea tile (tf32 bits), stride 68 — STREAMING loads (evict-first)
    for (int f = tid; f < TILE_E * 16; f += 128) {
        int r = f >> 4, q = f & 15;
        float4 v = __ldcs(reinterpret_cast<const float4*>(ea + (size_t)(base + r) * 64) + q);
        uint4 t;
        t.x = f2tf32(v.x); t.y = f2tf32(v.y); t.z = f2tf32(v.z); t.w = f2tf32(v.w);
        *reinterpret_cast<uint4*>(ea_s + r * EA_STR + q * 4) = t;
    }
    // stage B = WE (row-major [k][n]) as tf32 bits, stride 72
    for (int f = tid; f < 64 * 16; f += 128) {
        int k = f >> 4, q = f & 15;
        float4 v = reinterpret_cast<const float4*>(WE + (size_t)k * 64)[q];
        uint4 t;
        t.x = f2tf32(v.x); t.y = f2tf32(v.y); t.z = f2tf32(v.z); t.w = f2tf32(v.w);
        *reinterpret_cast<uint4*>(w_s + k * W_STR + q * 4) = t;
    }
    __syncthreads();

    const int lane = tid & 31;
    const int warp = tid >> 5;
    const int g  = lane >> 2;   // 0..7
    const int tg = lane & 3;    // 0..3
    const int wrow = warp * 16; // this warp's 16 edges

    // ---- Phase A: E = ea @ WE via m16n8k8 tf32 mma (one m-tile per warp) ----
    float acc[8][4];
    #pragma unroll
    for (int nt = 0; nt < 8; nt++)
        #pragma unroll
        for (int j = 0; j < 4; j++) acc[nt][j] = 0.0f;

    #pragma unroll
    for (int k8 = 0; k8 < 8; k8++) {
        const int r0 = wrow + g;
        uint32_t a0 = ea_s[(r0)     * EA_STR + k8 * 8 + tg];
        uint32_t a1 = ea_s[(r0 + 8) * EA_STR + k8 * 8 + tg];
        uint32_t a2 = ea_s[(r0)     * EA_STR + k8 * 8 + tg + 4];
        uint32_t a3 = ea_s[(r0 + 8) * EA_STR + k8 * 8 + tg + 4];
        #pragma unroll
        for (int nt = 0; nt < 8; nt++) {
            uint32_t b0 = w_s[(k8 * 8 + tg)     * W_STR + nt * 8 + g];
            uint32_t b1 = w_s[(k8 * 8 + tg + 4) * W_STR + nt * 8 + g];
            mma_tf32(acc[nt], a0, a1, a2, a3, b0, b1);
        }
    }

    // ---- store E (+bias) into this warp's own rows (no sync needed) ----
    #pragma unroll
    for (int rr = 0; rr < 2; rr++) {
        const int row = wrow + rr * 8 + g;
        #pragma unroll
        for (int nt = 0; nt < 8; nt++) {
            const int c0 = nt * 8 + tg * 2;
            float2 bb = *reinterpret_cast<const float2*>(bias_s + c0);
            *reinterpret_cast<float2*>(E_s + row * EA_STR + c0) =
                make_float2(acc[nt][rr * 2 + 0] + bb.x,
                            acc[nt][rr * 2 + 1] + bb.y);
        }
    }
    __syncthreads();

    // ---- Phase B: per (edge, head): score + scatter, all float4 ----
    #pragma unroll
    for (int pass = 0; pass < 2; pass++) {
        const int le = pass * 32 + (tid >> 2);
        const int h  = tid & 3;
        const int src = si_s[le];
        const int dst = di_s[le];

        const float4* Kp = reinterpret_cast<const float4*>(g_K + (size_t)src * 64 + h * 16);
        const float4* Qp = reinterpret_cast<const float4*>(g_Q + (size_t)dst * 64 + h * 16);
        const float4* Ep = reinterpret_cast<const float4*>(E_s + le * EA_STR + h * 16);

        float p = 0.0f;
        #pragma unroll
        for (int q = 0; q < 4; q++) {
            float4 k = Kp[q];
            float4 qv = Qp[q];
            float4 e = Ep[q];
            p += k.x * qv.x * e.x + k.y * qv.y * e.y + k.z * qv.z * e.z + k.w * qv.w * e.w;
        }
        float s = __expf(fminf(fmaxf(p * 0.25f, -5.0f), 5.0f));

        const float4* Vp = reinterpret_cast<const float4*>(g_V + (size_t)src * 64 + h * 16);
        float* ob = out + (size_t)dst * 64 + h * 16;
        #pragma unroll
        for (int q = 0; q < 4; q++) {
            float4 v = Vp[q];
            red_add_v4(ob + q * 4, v.x * s, v.y * s, v.z * s, v.w * s);
        }
        // Z: one red.v4 per edge (gather the quad's 4 head scores to h==0 lane)
        const int qbase = (tid & 31) & ~3;
        float s0 = __shfl_sync(0xffffffffu, s, qbase);
        float s1 = __shfl_sync(0xffffffffu, s, qbase + 1);
        float s2 = __shfl_sync(0xffffffffu, s, qbase + 2);
        float s3 = __shfl_sync(0xffffffffu, s, qbase + 3);
        if (h == 0)
            red_add_v4(g_Z + (size_t)dst * 4, s0, s1, s2, s3);
    }
}

// ---------------- finalize ----------------
__global__ void finalize_kernel(float* __restrict__ out) {
    int i = blockIdx.x * blockDim.x + threadIdx.x;
    if (i < N_NODES * HD) {
        int n = i >> 6;
        int h = (i >> 4) & 3;
        out[i] = out[i] / (g_Z[n * 4 + h] + 1e-6f);
    }
}

// ---------------- launch ----------------
extern "C" void kernel_launch(void* const* d_in, const int* in_sizes, int n_in,
                              void* d_out, int out_size) {
    const float* x   = (const float*)d_in[0];
    const float* ea  = (const float*)d_in[1];
    const int*   ei  = (const int*)  d_in[2];
    const float* WQ  = (const float*)d_in[3];
    const float* bQ  = (const float*)d_in[4];
    const float* WK  = (const float*)d_in[5];
    const float* bK  = (const float*)d_in[6];
    const float* WE  = (const float*)d_in[7];
    const float* bE  = (const float*)d_in[8];
    const float* WV  = (const float*)d_in[9];
    const float* bV  = (const float*)d_in[10];
    float* out = (float*)d_out;

    static_assert(EDGE_SMEM_FLOATS * 4 * 5 < 228 * 1024, "smem occupancy");
    cudaFuncSetAttribute(edge_kernel, cudaFuncAttributeMaxDynamicSharedMemorySize,
                         EDGE_SMEM_FLOATS * (int)sizeof(float));
    cudaFuncSetAttribute(proj_kernel, cudaFuncAttributeMaxDynamicSharedMemorySize,
                         PROJ_SMEM_FLOATS * (int)sizeof(float));

    zero_kernel<<<(N_NODES * HD + 255) / 256, 256>>>(out);
    {
        dim3 grid((N_NODES + 127) / 128, 3);
        proj_kernel<<<grid, 128, PROJ_SMEM_FLOATS * sizeof(float)>>>(x, WQ, bQ, WK, bK, WV, bV);
    }
    edge_kernel<<<N_EDGES / TILE_E, 128, EDGE_SMEM_FLOATS * sizeof(float)>>>(ea, ei, WE, bE, out);
    finalize_kernel<<<(N_NODES * HD + 255) / 256, 256>>>(out);
}